// round 1
// baseline (speedup 1.0000x reference)
#include <cuda_runtime.h>

// ConstantCurrentLIFEncoder: 100 steps of LIF dynamics with constant input.
//   v' = v + 0.1f * ((0 - v) + I)
//   z  = (v' - 1.0f > 0) ? 1 : 0
//   v  = v' - z * (v' - 0)
// Input:  [64, 8192] f32 (524288 elems)
// Output: [100, 64, 8192] f32 spikes (52428800 elems)

#define N_ELEMS   524288
#define N_VEC     (N_ELEMS / 4)   // 131072 float4 lanes
#define SEQ_LEN   100

__global__ void __launch_bounds__(256)
lif_encoder_kernel(const float* __restrict__ in, float* __restrict__ out) {
    const int idx = blockIdx.x * blockDim.x + threadIdx.x;
    if (idx >= N_VEC) return;

    const float4 I = __ldg(reinterpret_cast<const float4*>(in) + idx);

    float vx = 0.0f, vy = 0.0f, vz = 0.0f, vw = 0.0f;

    float4* o = reinterpret_cast<float4*>(out) + idx;

    #pragma unroll 5
    for (int t = 0; t < SEQ_LEN; t++) {
        // integrate (match reference op order: dv = 0.1 * ((0 - v) + I); v += dv)
        vx = vx + 0.1f * ((0.0f - vx) + I.x);
        vy = vy + 0.1f * ((0.0f - vy) + I.y);
        vz = vz + 0.1f * ((0.0f - vz) + I.z);
        vw = vw + 0.1f * ((0.0f - vw) + I.w);

        float4 s;
        s.x = (vx - 1.0f > 0.0f) ? 1.0f : 0.0f;
        s.y = (vy - 1.0f > 0.0f) ? 1.0f : 0.0f;
        s.z = (vz - 1.0f > 0.0f) ? 1.0f : 0.0f;
        s.w = (vw - 1.0f > 0.0f) ? 1.0f : 0.0f;

        // reset: v = v - z * (v - 0)
        vx = vx - s.x * vx;
        vy = vy - s.y * vy;
        vz = vz - s.z * vz;
        vw = vw - s.w * vw;

        // streaming store: output (210 MB) has no reuse, bypass L2 persistence
        __stcs(o + (size_t)t * N_VEC, s);
    }
}

extern "C" void kernel_launch(void* const* d_in, const int* in_sizes, int n_in,
                              void* d_out, int out_size) {
    const float* in = (const float*)d_in[0];
    float* out = (float*)d_out;

    const int threads = 256;
    const int blocks = (N_VEC + threads - 1) / threads;  // 512
    lif_encoder_kernel<<<blocks, threads>>>(in, out);
}